// round 6
// baseline (speedup 1.0000x reference)
#include <cuda_runtime.h>
#include <cstdint>

// DepthDeformConv: modulated deformable conv 3x3, s=1, p=1, d=1.
// B=4, C=64, H=W=128, O=64, K=9, fp32. Output (4,64,128,128) fp32.
//
// K0: repack input NCHW -> channel-grouped NHWC16: g_in16[b][cg][y][x][16]
//     (cg = c/16). A bilinear tap for one 16-channel chunk = contiguous 64B.
// K1: permute weights to col-row order r = k*16 + c_local per chunk:
//     g_wt[cc*144 + k*16 + cl][o].
// K2: main. One block per (b,y): 512 blocks x 256 threads, 2 blocks/SM.
//     Per chunk (16 c x 9 k = 144 rows):
//       - stage weights [144][64] -> smem (coalesced)
//       - gather: 8-lane groups, job = (k, pix); lane = channel pair ->
//         4 x LDG.64 per job-lane (dense 64B taps), bilinear, STS.32 x2
//         into XOR-swizzled col[r][pix^sw] (conflict-free)
//       - FMA: warp = 16-o group x ck-half, lane = 4-pix group; weight
//         LDS.128 broadcast gives o-pairs pre-packed for fma.rn.f32x2
//       - final: 2-way ck reduction via smem, bias, STG.128.

#define HW 128
#define PLANE 16384
#define CIN 64
#define OOUT 64
#define CKTOT 576
#define CHUNK 144           // 16 c * 9 k
#define NCHUNK 4
#define NTHREADS 256

#define OFF_W   73728                        // col: [0, 73728)
#define SMEM_TOTAL (73728 + CHUNK * 64 * 4)  // 110592

typedef unsigned long long ull;

__device__ float g_in16[4 * 4 * PLANE * 16];   // 16 MB: [b][cg][y*128+x][16]
__device__ float g_wt[CKTOT * OOUT];           // permuted weights

__device__ __forceinline__ ull pack2(float lo, float hi) {
    ull d;
    asm("mov.b64 %0, {%1, %2};" : "=l"(d) : "f"(lo), "f"(hi));
    return d;
}
__device__ __forceinline__ float2 unpack2(ull v) {
    float2 r;
    asm("mov.b64 {%0, %1}, %2;" : "=f"(r.x), "=f"(r.y) : "l"(v));
    return r;
}
__device__ __forceinline__ ull fma2(ull a, ull b, ull c) {
    ull d;
    asm("fma.rn.f32x2 %0, %1, %2, %3;" : "=l"(d) : "l"(a), "l"(b), "l"(c));
    return d;
}
__device__ __forceinline__ ull add2(ull a, ull b) {
    ull d;
    asm("add.rn.f32x2 %0, %1, %2;" : "=l"(d) : "l"(a), "l"(b));
    return d;
}

// ---------------- K0: NCHW -> NHWC16 ----------------
__global__ __launch_bounds__(256) void k_nhwc(const float* __restrict__ in) {
    __shared__ float t[64][129];
    const int bid = blockIdx.x;
    const int y = bid & 127, b = bid >> 7;
    const int tid = threadIdx.x;
    const float* ib = in + (size_t)b * CIN * PLANE + y * HW;
    #pragma unroll 8
    for (int it = 0; it < 32; it++) {
        int i = tid + it * 256;
        int c = i >> 7, x = i & 127;
        t[c][x] = __ldg(ib + c * PLANE + x);
    }
    __syncthreads();
    #pragma unroll 8
    for (int it = 0; it < 32; it++) {
        int i = tid + it * 256;
        int cl = i & 15, x = (i >> 4) & 127, cg = i >> 11;
        g_in16[(((size_t)(b * 4 + cg)) * PLANE + y * HW + x) * 16 + cl] = t[cg * 16 + cl][x];
    }
}

// ---------------- K1: weight permute ----------------
// g_wt[(cc*144 + k*16 + cl)*64 + o] = weight[o*576 + (cc*16+cl)*9 + k]
__global__ __launch_bounds__(256) void k_prep(const float* __restrict__ w) {
    int idx = blockIdx.x * 256 + threadIdx.x;
    if (idx >= OOUT * CKTOT) return;
    int o = idx / CKTOT, rem = idx - o * CKTOT;
    int c = rem / 9, k = rem - c * 9;
    int cc = c >> 4, cl = c & 15;
    g_wt[(cc * CHUNK + k * 16 + cl) * OOUT + o] = w[idx];
}

// ---------------- K2: main ----------------
extern __shared__ char smraw[];

__global__ __launch_bounds__(NTHREADS, 2)
void ddc_main(const float* __restrict__ offset,
              const float* __restrict__ mask,
              const float* __restrict__ bias,
              float* __restrict__ out)
{
    float* col   = (float*)smraw;              // [144][128] swizzled
    float* wsm_t = (float*)(smraw + OFF_W);    // [144][64]

    const int tid = threadIdx.x;
    const int bid = blockIdx.x;
    const int y = bid & 127;
    const int b = bid >> 7;
    const int wid  = tid >> 5;
    const int lane = tid & 31;
    const int og   = wid & 3;      // o-group: o base = og*16
    const int ckh  = wid >> 2;     // ck half
    const int grp  = tid >> 3;     // gather group 0..31
    const int p    = tid & 7;      // channel pair within group

    ull acc[8][4];
    #pragma unroll
    for (int j = 0; j < 8; j++)
        #pragma unroll
        for (int q = 0; q < 4; q++) acc[j][q] = 0ULL;

    for (int cc = 0; cc < NCHUNK; cc++) {
        __syncthreads();    // previous FMA phase done reading col/wsm_t

        // ---- stage permuted weight chunk [144][64] ----
        {
            const float4* src = (const float4*)(g_wt + cc * CHUNK * OOUT);
            float4* dst = (float4*)wsm_t;
            #pragma unroll
            for (int i = 0; i < 9; i++)
                dst[tid + i * NTHREADS] = src[tid + i * NTHREADS];
        }

        // ---- gather: 1152 (k,pix) jobs; 8-lane groups, lane = ch pair ----
        const float2* nb = (const float2*)g_in16 + ((size_t)(b * 4 + cc)) * PLANE * 8;
        #pragma unroll 2
        for (int j = grp; j < 9 * HW; j += 32) {
            int pix = j & 127;
            int k   = j >> 7;                  // 0..8
            int ky  = k / 3;
            int kx  = k - ky * 3;

            int ob = ((b * 18 + 2 * k) * HW + y) * HW + pix;
            float oy = __ldg(offset + ob);
            float ox = __ldg(offset + ob + PLANE);
            float m  = __ldg(mask + ((b * 9 + k) * HW + y) * HW + pix);

            float py = (float)(y - 1 + ky) + oy;
            float px = (float)(pix - 1 + kx) + ox;
            float y0f = floorf(py), x0f = floorf(px);
            int y0 = (int)y0f, x0 = (int)x0f;
            float wy = py - y0f, wx = px - x0f;
            int y1 = y0 + 1, x1 = x0 + 1;

            float vy0 = (y0 >= 0 && y0 < HW) ? 1.f : 0.f;
            float vy1 = (y1 >= 0 && y1 < HW) ? 1.f : 0.f;
            float vx0 = (x0 >= 0 && x0 < HW) ? 1.f : 0.f;
            float vx1 = (x1 >= 0 && x1 < HW) ? 1.f : 0.f;
            int yc0 = min(max(y0, 0), HW - 1);
            int yc1 = min(max(y1, 0), HW - 1);
            int xc0 = min(max(x0, 0), HW - 1);
            int xc1 = min(max(x1, 0), HW - 1);

            float w00 = (1.f - wy) * (1.f - wx) * m * vy0 * vx0;
            float w01 = (1.f - wy) * wx         * m * vy0 * vx1;
            float w10 = wy         * (1.f - wx) * m * vy1 * vx0;
            float w11 = wy         * wx         * m * vy1 * vx1;

            const float2* p00 = nb + (yc0 * HW + xc0) * 8 + p;
            const float2* p01 = nb + (yc0 * HW + xc1) * 8 + p;
            const float2* p10 = nb + (yc1 * HW + xc0) * 8 + p;
            const float2* p11 = nb + (yc1 * HW + xc1) * 8 + p;
            float2 t00 = __ldg(p00);
            float2 t01 = __ldg(p01);
            float2 t10 = __ldg(p10);
            float2 t11 = __ldg(p11);

            float vx_ = w00 * t00.x + w01 * t01.x + w10 * t10.x + w11 * t11.x;
            float vy_ = w00 * t00.y + w01 * t01.y + w10 * t10.y + w11 * t11.y;

            int r = k * 16 + 2 * p;            // col rows r, r+1
            int sw = (((unsigned)r >> 1) & 7) << 2;
            int psw = pix ^ sw;
            col[r * HW + psw]       = vx_;
            col[(r + 1) * HW + psw] = vy_;
        }
        __syncthreads();

        // ---- FMA: ck half [ckh*72, +72), 18 iters of 4 ck ----
        #pragma unroll 1
        for (int ck = ckh * 72; ck < ckh * 72 + 72; ck += 4) {
            #pragma unroll
            for (int u = 0; u < 4; u++) {
                int row = ck + u;
                int sw = (((unsigned)row >> 1) & 7) << 2;
                float4 cq = *(const float4*)(col + row * HW + ((lane * 4) ^ sw));
                ull cp0 = pack2(cq.x, cq.x);
                ull cp1 = pack2(cq.y, cq.y);
                ull cp2 = pack2(cq.z, cq.z);
                ull cp3 = pack2(cq.w, cq.w);
                const float* wrow = wsm_t + row * OOUT + og * 16;
                #pragma unroll
                for (int j2 = 0; j2 < 4; j2++) {
                    float4 wq = *(const float4*)(wrow + j2 * 4);  // broadcast
                    ull wp0 = pack2(wq.x, wq.y);
                    ull wp1 = pack2(wq.z, wq.w);
                    int j = j2 * 2;
                    acc[j][0] = fma2(wp0, cp0, acc[j][0]);
                    acc[j][1] = fma2(wp0, cp1, acc[j][1]);
                    acc[j][2] = fma2(wp0, cp2, acc[j][2]);
                    acc[j][3] = fma2(wp0, cp3, acc[j][3]);
                    acc[j+1][0] = fma2(wp1, cp0, acc[j+1][0]);
                    acc[j+1][1] = fma2(wp1, cp1, acc[j+1][1]);
                    acc[j+1][2] = fma2(wp1, cp2, acc[j+1][2]);
                    acc[j+1][3] = fma2(wp1, cp3, acc[j+1][3]);
                }
            }
        }
    }

    // ---- reduction across the 2 ck halves (reuse wsm_t area) ----
    ull* pr = (ull*)(smraw + OFF_W);   // [32 o-pairs][128 pix] u64 = 32KB
    __syncthreads();
    if (ckh == 1) {
        #pragma unroll
        for (int j = 0; j < 8; j++) {
            ull* row = pr + (og * 8 + j) * 128 + lane * 4;
            row[0] = acc[j][0]; row[1] = acc[j][1];
            row[2] = acc[j][2]; row[3] = acc[j][3];
        }
    }
    __syncthreads();
    if (ckh == 0) {
        #pragma unroll
        for (int j = 0; j < 8; j++) {
            const ull* row = pr + (og * 8 + j) * 128 + lane * 4;
            int o0 = og * 16 + 2 * j;
            float bv0 = __ldg(bias + o0);
            float bv1 = __ldg(bias + o0 + 1);
            float4 re, ro;
            float2 v;
            v = unpack2(add2(acc[j][0], row[0])); re.x = v.x + bv0; ro.x = v.y + bv1;
            v = unpack2(add2(acc[j][1], row[1])); re.y = v.x + bv0; ro.y = v.y + bv1;
            v = unpack2(add2(acc[j][2], row[2])); re.z = v.x + bv0; ro.z = v.y + bv1;
            v = unpack2(add2(acc[j][3], row[3])); re.w = v.x + bv0; ro.w = v.y + bv1;
            size_t base = (size_t)(b * OOUT + o0) * PLANE + y * HW + lane * 4;
            *(float4*)(out + base)         = re;
            *(float4*)(out + base + PLANE) = ro;
        }
    }
}

extern "C" void kernel_launch(void* const* d_in, const int* in_sizes, int n_in,
                              void* d_out, int out_size)
{
    const float* input  = (const float*)d_in[0];
    // d_in[1] = depth, unused by the reference computation
    const float* offset = (const float*)d_in[2];
    const float* mask   = (const float*)d_in[3];
    const float* weight = (const float*)d_in[4];
    const float* bias   = (const float*)d_in[5];
    float* out = (float*)d_out;

    cudaFuncSetAttribute(ddc_main,
                         cudaFuncAttributeMaxDynamicSharedMemorySize, SMEM_TOTAL);

    k_nhwc<<<512, 256>>>(input);
    k_prep<<<(OOUT * CKTOT + 255) / 256, 256>>>(weight);
    ddc_main<<<512, NTHREADS, SMEM_TOTAL>>>(offset, mask, bias, out);
}

// round 7
// speedup vs baseline: 1.0589x; 1.0589x over previous
#include <cuda_runtime.h>
#include <cstdint>

// DepthDeformConv: modulated deformable conv 3x3, s=1, p=1, d=1.
// B=4, C=64, H=W=128, O=64, K=9, fp32. Output (4,64,128,128) fp32.
//
// K0: repack input NCHW -> NHWC8: g_in8[b][g][y*128+x][8]  (g = c/8).
//     One bilinear tap for an 8-channel chunk = contiguous 32B (1 sector).
// K1: permute weights to row order r = k*8 + cl per chunk:
//     g_wt[(cc*72 + k*8 + cl)*64 + o].
// K2: main. One block per (b,y): 512 blocks x 256 threads, 2 blocks/SM.
//     - META (once): 1152 (k,pix) jobs -> presc. indices int4 + weights float4
//     - per chunk cc (8 chunks of 8 channels = 72 col rows):
//         stage weights [72][64] -> smem
//         gather: 4-lane groups (lane = ch pair); meta via broadcast LDS,
//                 4 x LDG.64 dense taps, 2 STS.32 into XOR-swizzled col
//         FMA: warp = 16-o group x ck-half, lane = 4-pix group; weight
//              LDS.128 broadcast -> o-pairs pre-packed for fma.rn.f32x2
//     - final: 2-way ck reduction via smem, bias, STG.128.

#define HW 128
#define PLANE 16384
#define CIN 64
#define OOUT 64
#define CKTOT 576
#define NJOBS 1152          // 9 * 128
#define RPC 72              // rows per chunk: 8 c * 9 k
#define NCHUNK 8
#define NTHREADS 256

#define OFF_W  36864                    // col: [0, 36864)
#define OFF_MI (36864 + 18432)          // 55296: int4[1152]
#define OFF_MW (OFF_MI + 18432)         // 73728: float4[1152]
#define SMEM_TOTAL (OFF_MW + 18432)     // 92160

typedef unsigned long long ull;

__device__ float g_in8[4 * 8 * PLANE * 8];   // 16 MB
__device__ float g_wt[CKTOT * OOUT];

__device__ __forceinline__ ull pack2(float lo, float hi) {
    ull d;
    asm("mov.b64 %0, {%1, %2};" : "=l"(d) : "f"(lo), "f"(hi));
    return d;
}
__device__ __forceinline__ float2 unpack2(ull v) {
    float2 r;
    asm("mov.b64 {%0, %1}, %2;" : "=f"(r.x), "=f"(r.y) : "l"(v));
    return r;
}
__device__ __forceinline__ ull fma2(ull a, ull b, ull c) {
    ull d;
    asm("fma.rn.f32x2 %0, %1, %2, %3;" : "=l"(d) : "l"(a), "l"(b), "l"(c));
    return d;
}
__device__ __forceinline__ ull add2(ull a, ull b) {
    ull d;
    asm("add.rn.f32x2 %0, %1, %2;" : "=l"(d) : "l"(a), "l"(b));
    return d;
}

// ---------------- K0: NCHW -> NHWC8 ----------------
__global__ __launch_bounds__(256) void k_nhwc(const float* __restrict__ in) {
    __shared__ float t[64][129];
    const int bid = blockIdx.x;
    const int y = bid & 127, b = bid >> 7;
    const int tid = threadIdx.x;
    const float* ib = in + (size_t)b * CIN * PLANE + y * HW;
    #pragma unroll 8
    for (int it = 0; it < 32; it++) {
        int i = tid + it * 256;
        int c = i >> 7, x = i & 127;
        t[c][x] = __ldg(ib + c * PLANE + x);
    }
    __syncthreads();
    #pragma unroll 8
    for (int it = 0; it < 32; it++) {
        int i = tid + it * 256;
        int cl = i & 7, x = (i >> 3) & 127, g = i >> 10;
        g_in8[(((size_t)(b * 8 + g)) * PLANE + y * HW + x) * 8 + cl] = t[g * 8 + cl][x];
    }
}

// ---------------- K1: weight permute ----------------
__global__ __launch_bounds__(256) void k_prep(const float* __restrict__ w) {
    int idx = blockIdx.x * 256 + threadIdx.x;
    if (idx >= OOUT * CKTOT) return;
    int o = idx / CKTOT, rem = idx - o * CKTOT;
    int c = rem / 9, k = rem - c * 9;
    int cc = c >> 3, cl = c & 7;
    g_wt[(cc * RPC + k * 8 + cl) * OOUT + o] = w[idx];
}

// ---------------- K2: main ----------------
extern __shared__ char smraw[];

__global__ __launch_bounds__(NTHREADS, 2)
void ddc_main(const float* __restrict__ offset,
              const float* __restrict__ mask,
              const float* __restrict__ bias,
              float* __restrict__ out)
{
    float*  col    = (float*)smraw;              // [72][128] swizzled
    float*  wsm    = (float*)(smraw + OFF_W);    // [72][64]
    int4*   meta_i = (int4*)(smraw + OFF_MI);
    float4* meta_w = (float4*)(smraw + OFF_MW);

    const int tid = threadIdx.x;
    const int bid = blockIdx.x;
    const int y = bid & 127;
    const int b = bid >> 7;
    const int wid  = tid >> 5;
    const int lane = tid & 31;
    const int og   = wid & 3;      // o-group: o base = og*16
    const int ckh  = wid >> 2;     // ck half
    const int grp  = tid >> 2;     // gather group 0..63
    const int p    = tid & 3;      // channel pair within group

    // ---- META: 1152 jobs, once per block ----
    for (int i = tid; i < NJOBS; i += NTHREADS) {
        int pix = i & 127;
        int k   = i >> 7;
        int ky  = k / 3;
        int kx  = k - ky * 3;

        int ob = ((b * 18 + 2 * k) * HW + y) * HW + pix;
        float oy = __ldg(offset + ob);
        float ox = __ldg(offset + ob + PLANE);
        float m  = __ldg(mask + ((b * 9 + k) * HW + y) * HW + pix);

        float py = (float)(y - 1 + ky) + oy;
        float px = (float)(pix - 1 + kx) + ox;
        float y0f = floorf(py), x0f = floorf(px);
        int y0 = (int)y0f, x0 = (int)x0f;
        float wy = py - y0f, wx = px - x0f;
        int y1 = y0 + 1, x1 = x0 + 1;

        float vy0 = (y0 >= 0 && y0 < HW) ? 1.f : 0.f;
        float vy1 = (y1 >= 0 && y1 < HW) ? 1.f : 0.f;
        float vx0 = (x0 >= 0 && x0 < HW) ? 1.f : 0.f;
        float vx1 = (x1 >= 0 && x1 < HW) ? 1.f : 0.f;
        int yc0 = min(max(y0, 0), HW - 1);
        int yc1 = min(max(y1, 0), HW - 1);
        int xc0 = min(max(x0, 0), HW - 1);
        int xc1 = min(max(x1, 0), HW - 1);

        float4 w;
        w.x = (1.f - wy) * (1.f - wx) * m * vy0 * vx0;
        w.y = (1.f - wy) * wx         * m * vy0 * vx1;
        w.z = wy         * (1.f - wx) * m * vy1 * vx0;
        w.w = wy         * wx         * m * vy1 * vx1;

        // pre-scaled to float2 units (8 floats = 4 float2 per pixel)
        meta_i[i] = make_int4((yc0 * HW + xc0) * 4, (yc0 * HW + xc1) * 4,
                              (yc1 * HW + xc0) * 4, (yc1 * HW + xc1) * 4);
        meta_w[i] = w;
    }

    ull acc[8][4];
    #pragma unroll
    for (int j = 0; j < 8; j++)
        #pragma unroll
        for (int q = 0; q < 4; q++) acc[j][q] = 0ULL;

    for (int cc = 0; cc < NCHUNK; cc++) {
        __syncthreads();    // meta ready / previous FMA done with col+wsm

        // ---- stage permuted weight chunk [72][64] ----
        {
            const float4* src = (const float4*)(g_wt + cc * RPC * OOUT);
            float4* dst = (float4*)wsm;
            #pragma unroll
            for (int i = tid; i < RPC * OOUT / 4; i += NTHREADS)
                dst[i] = src[i];
        }

        // ---- gather: 1152 jobs x 4 lanes; 18 iters/thread ----
        const float2* nb = (const float2*)g_in8 + ((size_t)(b * 8 + cc)) * PLANE * 4;
        #pragma unroll 2
        for (int j = grp; j < NJOBS; j += 64) {
            int4   mi = meta_i[j];
            float4 mw = meta_w[j];
            float2 t00 = __ldg(nb + mi.x + p);
            float2 t01 = __ldg(nb + mi.y + p);
            float2 t10 = __ldg(nb + mi.z + p);
            float2 t11 = __ldg(nb + mi.w + p);

            float vx_ = mw.x * t00.x + mw.y * t01.x + mw.z * t10.x + mw.w * t11.x;
            float vy_ = mw.x * t00.y + mw.y * t01.y + mw.z * t10.y + mw.w * t11.y;

            int pix = j & 127;
            int r   = (j >> 7) * 8 + 2 * p;    // k*8 + 2p
            int psw = pix ^ (p << 3);
            col[r * HW + psw]       = vx_;
            col[(r + 1) * HW + psw] = vy_;
        }
        __syncthreads();

        // ---- FMA: ck half [ckh*36, +36), 9 iters of 4 rows ----
        #pragma unroll 1
        for (int ck = ckh * 36; ck < ckh * 36 + 36; ck += 4) {
            #pragma unroll
            for (int u = 0; u < 4; u++) {
                int row = ck + u;
                int sw = (((unsigned)row >> 1) & 3) << 3;
                float4 cq = *(const float4*)(col + row * HW + ((lane * 4) ^ sw));
                ull cp0 = pack2(cq.x, cq.x);
                ull cp1 = pack2(cq.y, cq.y);
                ull cp2 = pack2(cq.z, cq.z);
                ull cp3 = pack2(cq.w, cq.w);
                const float* wrow = wsm + row * OOUT + og * 16;
                #pragma unroll
                for (int j2 = 0; j2 < 4; j2++) {
                    float4 wq = *(const float4*)(wrow + j2 * 4);  // broadcast
                    ull wp0 = pack2(wq.x, wq.y);
                    ull wp1 = pack2(wq.z, wq.w);
                    int j = j2 * 2;
                    acc[j][0] = fma2(wp0, cp0, acc[j][0]);
                    acc[j][1] = fma2(wp0, cp1, acc[j][1]);
                    acc[j][2] = fma2(wp0, cp2, acc[j][2]);
                    acc[j][3] = fma2(wp0, cp3, acc[j][3]);
                    acc[j+1][0] = fma2(wp1, cp0, acc[j+1][0]);
                    acc[j+1][1] = fma2(wp1, cp1, acc[j+1][1]);
                    acc[j+1][2] = fma2(wp1, cp2, acc[j+1][2]);
                    acc[j+1][3] = fma2(wp1, cp3, acc[j+1][3]);
                }
            }
        }
    }

    // ---- reduction across the 2 ck halves (reuse col area) ----
    ull* pr = (ull*)smraw;   // [32 o-pairs][128 pix] u64 = 32768 B
    __syncthreads();
    if (ckh == 1) {
        #pragma unroll
        for (int j = 0; j < 8; j++) {
            ull* row = pr + (og * 8 + j) * 128 + lane * 4;
            row[0] = acc[j][0]; row[1] = acc[j][1];
            row[2] = acc[j][2]; row[3] = acc[j][3];
        }
    }
    __syncthreads();
    if (ckh == 0) {
        #pragma unroll
        for (int j = 0; j < 8; j++) {
            const ull* row = pr + (og * 8 + j) * 128 + lane * 4;
            int o0 = og * 16 + 2 * j;
            float bv0 = __ldg(bias + o0);
            float bv1 = __ldg(bias + o0 + 1);
            float4 re, ro;
            float2 v;
            v = unpack2(add2(acc[j][0], row[0])); re.x = v.x + bv0; ro.x = v.y + bv1;
            v = unpack2(add2(acc[j][1], row[1])); re.y = v.x + bv0; ro.y = v.y + bv1;
            v = unpack2(add2(acc[j][2], row[2])); re.z = v.x + bv0; ro.z = v.y + bv1;
            v = unpack2(add2(acc[j][3], row[3])); re.w = v.x + bv0; ro.w = v.y + bv1;
            size_t base = (size_t)(b * OOUT + o0) * PLANE + y * HW + lane * 4;
            *(float4*)(out + base)         = re;
            *(float4*)(out + base + PLANE) = ro;
        }
    }
}

extern "C" void kernel_launch(void* const* d_in, const int* in_sizes, int n_in,
                              void* d_out, int out_size)
{
    const float* input  = (const float*)d_in[0];
    // d_in[1] = depth, unused by the reference computation
    const float* offset = (const float*)d_in[2];
    const float* mask   = (const float*)d_in[3];
    const float* weight = (const float*)d_in[4];
    const float* bias   = (const float*)d_in[5];
    float* out = (float*)d_out;

    cudaFuncSetAttribute(ddc_main,
                         cudaFuncAttributeMaxDynamicSharedMemorySize, SMEM_TOTAL);

    k_nhwc<<<512, 256>>>(input);
    k_prep<<<(OOUT * CKTOT + 255) / 256, 256>>>(weight);
    ddc_main<<<512, NTHREADS, SMEM_TOTAL>>>(offset, mask, bias, out);
}